// round 8
// baseline (speedup 1.0000x reference)
#include <cuda_runtime.h>

// CustomLinearRNN via chunked parallel scan (R7: packed-pair SIMT GEMMs).
// h_t = A4 h_{t-1} + A3 x_t ; known_t = A1 x_t + A2 h_{t-1}
//  ksq x5 : P = A4^32
//  K1 : UZ[t] = [A3;A1] x_t   (persistent, grid 148)
//  K2 : per-chunk zero-state scan -> W_i   (grid 128, one CTA/chunk)
//  K3 : boundary scan s_{i+1} = P s_i + W_i
//  K4 : rerun chunks from s_i, fused known  (grid 128)

#define T_STEPS 4096
#define KDIM 64
#define HDIM 128
#define BDIM 128
#define CHUNK 32
#define NCHUNK 128
#define K1_GRID 148

typedef unsigned long long u64;

// stacked scratch: rows 0..127 = U = A3 x, rows 128..191 = Z = A1 x
__device__ float g_UZ[(size_t)T_STEPS * 192 * BDIM];
__device__ float g_W[(size_t)NCHUNK * HDIM * BDIM];
__device__ float g_S[(size_t)NCHUNK * HDIM * BDIM];
__device__ float g_Pa[HDIM * HDIM];
__device__ float g_Pb[HDIM * HDIM];

__device__ __forceinline__ u64 ffma2(u64 a, u64 b, u64 c) {
    u64 d; asm("fma.rn.f32x2 %0, %1, %2, %3;" : "=l"(d) : "l"(a), "l"(b), "l"(c));
    return d;
}
__device__ __forceinline__ u64 fadd2(u64 a, u64 b) {
    u64 d; asm("add.rn.f32x2 %0, %1, %2;" : "=l"(d) : "l"(a), "l"(b));
    return d;
}
__device__ __forceinline__ u64 pk2s(float v) {
    u64 u; asm("mov.b64 %0, {%1, %1};" : "=l"(u) : "f"(v)); return u;
}
__device__ __forceinline__ void upk2(float& lo, float& hi, u64 u) {
    asm("mov.b64 {%0, %1}, %2;" : "=f"(lo), "=f"(hi) : "l"(u));
}

// ---------------- Ksq: dst = src * src (128x128) ----------------
__global__ __launch_bounds__(128, 1)
void k_sq(const float* __restrict__ src, float* __restrict__ dst)
{
    __shared__ float row[HDIM];
    const int r = blockIdx.x, c = threadIdx.x;
    row[c] = src[r * HDIM + c];
    __syncthreads();
    float a0 = 0, a1 = 0, a2 = 0, a3 = 0;
    #pragma unroll 8
    for (int k = 0; k < HDIM; k += 4) {
        a0 = fmaf(row[k],     src[(k)     * HDIM + c], a0);
        a1 = fmaf(row[k + 1], src[(k + 1) * HDIM + c], a1);
        a2 = fmaf(row[k + 2], src[(k + 2) * HDIM + c], a2);
        a3 = fmaf(row[k + 3], src[(k + 3) * HDIM + c], a3);
    }
    dst[r * HDIM + c] = (a0 + a1) + (a2 + a3);
}

// ---------------- K1: UZ = [A3;A1] X, persistent ----------------
__global__ __launch_bounds__(256, 1)
void k1_ux(const float* __restrict__ x,
           const float* __restrict__ A3,
           const float* __restrict__ A1)
{
    extern __shared__ float sm[];
    float* sWt = sm;               // [kk 64][192] transposed stacked [A3;A1]
    float* sX  = sm + 64 * 192;    // [2][kk 64][128]

    const int tid = threadIdx.x;

    for (int idx = tid; idx < 192 * 64; idx += 256) {
        const int r = idx / 64, kk = idx % 64;
        sWt[kk * 192 + r] = (r < HDIM) ? A3[r * KDIM + kk]
                                       : A1[(r - HDIM) * KDIM + kk];
    }
    // preload first x tile
    {
        const float4* xg = (const float4*)(x + (size_t)blockIdx.x * KDIM * BDIM);
        float4* s0 = (float4*)sX;
        for (int idx = tid; idx < 2048; idx += 256) s0[idx] = xg[idx];
    }
    __syncthreads();

    const int ty = tid >> 4, tx = tid & 15;
    const int r0 = ty * 12, c0 = tx * 8;

    int it = 0;
    #pragma unroll 1
    for (int t = blockIdx.x; t < T_STEPS; t += K1_GRID, it ^= 1) {
        const int tn = t + K1_GRID;
        if (tn < T_STEPS) {
            const float4* xg = (const float4*)(x + (size_t)tn * KDIM * BDIM);
            float4* sn = (float4*)(sX + (it ^ 1) * 8192);
            for (int idx = tid; idx < 2048; idx += 256) sn[idx] = xg[idx];
        }
        const float* sXc = sX + it * 8192;

        u64 acc[12][4];
        #pragma unroll
        for (int m = 0; m < 12; m++)
            #pragma unroll
            for (int j = 0; j < 4; j++) acc[m][j] = 0ull;

        #pragma unroll 2
        for (int kk = 0; kk < 64; kk++) {
            const float4 w0 = *(const float4*)&sWt[kk * 192 + r0];
            const float4 w1 = *(const float4*)&sWt[kk * 192 + r0 + 4];
            const float4 w2 = *(const float4*)&sWt[kk * 192 + r0 + 8];
            const ulonglong2 xa = *(const ulonglong2*)&sXc[kk * 128 + c0];
            const ulonglong2 xb = *(const ulonglong2*)&sXc[kk * 128 + c0 + 4];
            const u64 xv[4] = {xa.x, xa.y, xb.x, xb.y};
            const float wv[12] = {w0.x, w0.y, w0.z, w0.w,
                                  w1.x, w1.y, w1.z, w1.w,
                                  w2.x, w2.y, w2.z, w2.w};
            #pragma unroll
            for (int m = 0; m < 12; m++) {
                const u64 ws = pk2s(wv[m]);
                #pragma unroll
                for (int j = 0; j < 4; j++)
                    acc[m][j] = ffma2(ws, xv[j], acc[m][j]);
            }
        }

        #pragma unroll
        for (int m = 0; m < 12; m++) {
            float* dst = &g_UZ[((size_t)t * 192 + r0 + m) * BDIM + c0];
            *(ulonglong2*)dst       = make_ulonglong2(acc[m][0], acc[m][1]);
            *((ulonglong2*)dst + 1) = make_ulonglong2(acc[m][2], acc[m][3]);
        }
        __syncthreads();
    }
}

// ---------------- K2: zero-state chunk scan -> g_W ----------------
__global__ __launch_bounds__(256, 1)
void k2_chunkzero(const float* __restrict__ A4)
{
    extern __shared__ float sm[];
    float* sA4t = sm;               // [kk 128][128 r]
    float* sH   = sm + 128 * 128;   // [2][kk 128][128 c]

    const int ic  = blockIdx.x;
    const int tid = threadIdx.x;
    const int ty = tid >> 4, tx = tid & 15;
    const int r0 = ty * 8, c0 = tx * 8;

    for (int idx = tid; idx < 128 * 128; idx += 256) {
        const int r = idx >> 7, kk = idx & 127;
        sA4t[kk * 128 + r] = A4[idx];
    }
    for (int idx = tid; idx < 128 * 128; idx += 256) sH[idx] = 0.0f;
    __syncthreads();

    #pragma unroll 1
    for (int c = 0; c < CHUNK; c++) {
        const int t = ic * CHUNK + c;
        const float* sHc = sH + (c & 1) * 16384;
        float*       sHn = sH + ((c + 1) & 1) * 16384;

        // acc initialized with u tile (h_t = u_t + A4 h_{t-1})
        u64 acc[8][4];
        #pragma unroll
        for (int m = 0; m < 8; m++) {
            const ulonglong2* up =
                (const ulonglong2*)&g_UZ[((size_t)t * 192 + r0 + m) * BDIM + c0];
            const ulonglong2 a = up[0], b = up[1];
            acc[m][0] = a.x; acc[m][1] = a.y; acc[m][2] = b.x; acc[m][3] = b.y;
        }

        #pragma unroll 2
        for (int kk = 0; kk < 128; kk++) {
            const float4 w0 = *(const float4*)&sA4t[kk * 128 + r0];
            const float4 w1 = *(const float4*)&sA4t[kk * 128 + r0 + 4];
            const ulonglong2 ha = *(const ulonglong2*)&sHc[kk * 128 + c0];
            const ulonglong2 hb = *(const ulonglong2*)&sHc[kk * 128 + c0 + 4];
            const u64 hv[4] = {ha.x, ha.y, hb.x, hb.y};
            const float wv[8] = {w0.x, w0.y, w0.z, w0.w, w1.x, w1.y, w1.z, w1.w};
            #pragma unroll
            for (int m = 0; m < 8; m++) {
                const u64 ws = pk2s(wv[m]);
                #pragma unroll
                for (int j = 0; j < 4; j++)
                    acc[m][j] = ffma2(ws, hv[j], acc[m][j]);
            }
        }

        if (c == CHUNK - 1) {
            #pragma unroll
            for (int m = 0; m < 8; m++) {
                float* dst = &g_W[((size_t)ic * HDIM + r0 + m) * BDIM + c0];
                *(ulonglong2*)dst       = make_ulonglong2(acc[m][0], acc[m][1]);
                *((ulonglong2*)dst + 1) = make_ulonglong2(acc[m][2], acc[m][3]);
            }
        } else {
            #pragma unroll
            for (int m = 0; m < 8; m++) {
                float* dst = &sHn[(r0 + m) * 128 + c0];
                *(ulonglong2*)dst       = make_ulonglong2(acc[m][0], acc[m][1]);
                *((ulonglong2*)dst + 1) = make_ulonglong2(acc[m][2], acc[m][3]);
            }
        }
        __syncthreads();
    }
}

// ---------------- K3: boundary scan, one CTA per b ----------------
__global__ __launch_bounds__(128, 1)
void k3_scan(const float* __restrict__ h0)
{
    extern __shared__ float sm[];
    float* sP = sm;                 // [r][130] padded
    float* sS = sm + 128 * 130;

    const int b = blockIdx.x;
    const int tid = threadIdx.x;

    for (int idx = tid; idx < 128 * 128; idx += 128) {
        const int r = idx >> 7, kk = idx & 127;
        sP[r * 130 + kk] = g_Pa[idx];
    }
    float s = h0[tid * BDIM + b];
    sS[tid] = s;
    __syncthreads();

    #pragma unroll 1
    for (int i = 0; i < NCHUNK; i++) {
        g_S[((size_t)i * HDIM + tid) * BDIM + b] = s;
        const float w = g_W[((size_t)i * HDIM + tid) * BDIM + b];
        const u64* s2 = (const u64*)sS;
        const u64* p2 = (const u64*)&sP[tid * 130];
        u64 a0 = 0ull, a1 = 0ull, a2 = 0ull, a3 = 0ull;
        #pragma unroll 4
        for (int m = 0; m < 64; m += 4) {
            a0 = ffma2(p2[m],     s2[m],     a0);
            a1 = ffma2(p2[m + 1], s2[m + 1], a1);
            a2 = ffma2(p2[m + 2], s2[m + 2], a2);
            a3 = ffma2(p2[m + 3], s2[m + 3], a3);
        }
        const u64 aa = fadd2(fadd2(a0, a1), fadd2(a2, a3));
        float lo, hi; upk2(lo, hi, aa);
        s = lo + hi + w;
        __syncthreads();
        sS[tid] = s;
        __syncthreads();
    }
}

// ---------------- K4: rerun chunks + fused known ----------------
__global__ __launch_bounds__(256, 1)
void k4_final(const float* __restrict__ A4,
              const float* __restrict__ A2,
              float* __restrict__ out_known,
              float* __restrict__ out_hidden)
{
    extern __shared__ float sm[];
    float* sWt = sm;                // [kk 128][192]: r<128 A4t, r>=128 A2t
    float* sH  = sm + 128 * 192;    // [2][kk 128][128 c]

    const int ic  = blockIdx.x;
    const int tid = threadIdx.x;
    const int ty = tid >> 4, tx = tid & 15;
    const int hr0 = ty * 8;   // h rows
    const int kr0 = ty * 4;   // known rows
    const int c0  = tx * 8;

    for (int idx = tid; idx < 192 * 128; idx += 256) {
        const int r = idx >> 7, kk = idx & 127;
        sWt[kk * 192 + r] = (r < HDIM) ? A4[r * HDIM + kk]
                                       : A2[(r - HDIM) * HDIM + kk];
    }
    {
        const float4* sg = (const float4*)&g_S[(size_t)ic * HDIM * BDIM];
        float4* sh = (float4*)sH;
        for (int idx = tid; idx < 4096; idx += 256) sh[idx] = sg[idx];
    }
    __syncthreads();

    #pragma unroll 1
    for (int c = 0; c < CHUNK; c++) {
        const int t = ic * CHUNK + c;
        const float* sHc = sH + (c & 1) * 16384;
        float*       sHn = sH + ((c + 1) & 1) * 16384;

        // acch init = u tile, acck init = z tile
        u64 acch[8][4], acck[4][4];
        #pragma unroll
        for (int m = 0; m < 8; m++) {
            const ulonglong2* up =
                (const ulonglong2*)&g_UZ[((size_t)t * 192 + hr0 + m) * BDIM + c0];
            const ulonglong2 a = up[0], b = up[1];
            acch[m][0] = a.x; acch[m][1] = a.y; acch[m][2] = b.x; acch[m][3] = b.y;
        }
        #pragma unroll
        for (int m = 0; m < 4; m++) {
            const ulonglong2* zp =
                (const ulonglong2*)&g_UZ[((size_t)t * 192 + 128 + kr0 + m) * BDIM + c0];
            const ulonglong2 a = zp[0], b = zp[1];
            acck[m][0] = a.x; acck[m][1] = a.y; acck[m][2] = b.x; acck[m][3] = b.y;
        }

        #pragma unroll 2
        for (int kk = 0; kk < 128; kk++) {
            const float4 w0 = *(const float4*)&sWt[kk * 192 + hr0];
            const float4 w1 = *(const float4*)&sWt[kk * 192 + hr0 + 4];
            const float4 wk = *(const float4*)&sWt[kk * 192 + 128 + kr0];
            const ulonglong2 ha = *(const ulonglong2*)&sHc[kk * 128 + c0];
            const ulonglong2 hb = *(const ulonglong2*)&sHc[kk * 128 + c0 + 4];
            const u64 hv[4] = {ha.x, ha.y, hb.x, hb.y};
            const float wh[8] = {w0.x, w0.y, w0.z, w0.w, w1.x, w1.y, w1.z, w1.w};
            const float wz[4] = {wk.x, wk.y, wk.z, wk.w};
            #pragma unroll
            for (int m = 0; m < 8; m++) {
                const u64 ws = pk2s(wh[m]);
                #pragma unroll
                for (int j = 0; j < 4; j++)
                    acch[m][j] = ffma2(ws, hv[j], acch[m][j]);
            }
            #pragma unroll
            for (int m = 0; m < 4; m++) {
                const u64 ws = pk2s(wz[m]);
                #pragma unroll
                for (int j = 0; j < 4; j++)
                    acck[m][j] = ffma2(ws, hv[j], acck[m][j]);
            }
        }

        // known_t
        #pragma unroll
        for (int m = 0; m < 4; m++) {
            float* dst = &out_known[((size_t)t * KDIM + kr0 + m) * BDIM + c0];
            *(ulonglong2*)dst       = make_ulonglong2(acck[m][0], acck[m][1]);
            *((ulonglong2*)dst + 1) = make_ulonglong2(acck[m][2], acck[m][3]);
        }
        // h_t -> out_hidden + next smem buffer
        #pragma unroll
        for (int m = 0; m < 8; m++) {
            float* dst = &out_hidden[((size_t)t * HDIM + hr0 + m) * BDIM + c0];
            const ulonglong2 v0 = make_ulonglong2(acch[m][0], acch[m][1]);
            const ulonglong2 v1 = make_ulonglong2(acch[m][2], acch[m][3]);
            *(ulonglong2*)dst       = v0;
            *((ulonglong2*)dst + 1) = v1;
            if (c < CHUNK - 1) {
                float* sdst = &sHn[(hr0 + m) * 128 + c0];
                *(ulonglong2*)sdst       = v0;
                *((ulonglong2*)sdst + 1) = v1;
            }
        }
        __syncthreads();
    }
}

// ---------------- host ----------------
extern "C" void kernel_launch(void* const* d_in, const int* in_sizes, int n_in,
                              void* d_out, int out_size)
{
    const float* x  = (const float*)d_in[0];
    const float* h0 = (const float*)d_in[1];
    const float* A1 = (const float*)d_in[2];
    const float* A2 = (const float*)d_in[3];
    const float* A3 = (const float*)d_in[4];
    const float* A4 = (const float*)d_in[5];

    float* out_known  = (float*)d_out;
    float* out_hidden = (float*)d_out + (size_t)T_STEPS * KDIM * BDIM;

    const int smem1 = (64 * 192 + 2 * 64 * 128) * 4;        // 114688
    const int smem2 = (128 * 128 + 2 * 128 * 128) * 4;      // 196608
    const int smem3 = (128 * 130 + 128) * 4;                // 67072
    const int smem4 = (128 * 192 + 2 * 128 * 128) * 4;      // 229376

    cudaFuncSetAttribute(k1_ux,        cudaFuncAttributeMaxDynamicSharedMemorySize, smem1);
    cudaFuncSetAttribute(k2_chunkzero, cudaFuncAttributeMaxDynamicSharedMemorySize, smem2);
    cudaFuncSetAttribute(k3_scan,      cudaFuncAttributeMaxDynamicSharedMemorySize, smem3);
    cudaFuncSetAttribute(k4_final,     cudaFuncAttributeMaxDynamicSharedMemorySize, smem4);

    float *pa, *pb;
    cudaGetSymbolAddress((void**)&pa, g_Pa);
    cudaGetSymbolAddress((void**)&pb, g_Pb);

    // ksq first so ncu -s 5 lands on k1 (launch #6)
    k_sq<<<HDIM, HDIM>>>(A4, pa);   // A4^2
    k_sq<<<HDIM, HDIM>>>(pa, pb);   // A4^4
    k_sq<<<HDIM, HDIM>>>(pb, pa);   // A4^8
    k_sq<<<HDIM, HDIM>>>(pa, pb);   // A4^16
    k_sq<<<HDIM, HDIM>>>(pb, pa);   // A4^32 -> g_Pa

    k1_ux<<<K1_GRID, 256, smem1>>>(x, A3, A1);
    k2_chunkzero<<<NCHUNK, 256, smem2>>>(A4);
    k3_scan<<<BDIM, 128, smem3>>>(h0);
    k4_final<<<NCHUNK, 256, smem4>>>(A4, A2, out_known, out_hidden);

    (void)in_sizes; (void)n_in; (void)out_size;
}

// round 11
// speedup vs baseline: 1.6080x; 1.6080x over previous
#include <cuda_runtime.h>
#include <cuda_fp16.h>

// CustomLinearRNN via chunked parallel scan; recurrence on mma.sync (HMMA).
//  ksq x5 : P = A4^32 (fp32 SIMT)
//  k1     : UZ[t] = [A3;A1] x_t (fp32 SIMT persistent) -> g_UZ[t][row][b]
//  k_rec(0): zero-state chunk scan -> g_W     (HMMA fp16 hi/lo split, 3 terms)
//  k3     : boundary scan s_{i+1} = P s_i + W_i (fp32 SIMT)
//  k_rec(1): rerun chunks from g_S -> out_hidden (HMMA)
//  k5     : known_t = Z_t + A2 h_{t-1}          (HMMA, parallel over t)

#define T_STEPS 4096
#define KDIM 64
#define HDIM 128
#define BDIM 128
#define CHUNK 32
#define NCHUNK 128
#define K1_GRID 148
#define SHS 136   // state smem stride in halves (16B-aligned rows, conflict-free)

typedef unsigned long long u64;
typedef unsigned int u32;

__device__ float g_UZ[(size_t)T_STEPS * 192 * BDIM];
__device__ float g_W[(size_t)NCHUNK * HDIM * BDIM];
__device__ float g_S[(size_t)NCHUNK * HDIM * BDIM];
__device__ float g_Pa[HDIM * HDIM];
__device__ float g_Pb[HDIM * HDIM];

// ---------- SIMT helpers ----------
__device__ __forceinline__ u64 ffma2(u64 a, u64 b, u64 c) {
    u64 d; asm("fma.rn.f32x2 %0, %1, %2, %3;" : "=l"(d) : "l"(a), "l"(b), "l"(c));
    return d;
}
__device__ __forceinline__ u64 fadd2(u64 a, u64 b) {
    u64 d; asm("add.rn.f32x2 %0, %1, %2;" : "=l"(d) : "l"(a), "l"(b));
    return d;
}
__device__ __forceinline__ u64 pk2s(float v) {
    u64 u; asm("mov.b64 %0, {%1, %1};" : "=l"(u) : "f"(v)); return u;
}
__device__ __forceinline__ void upk2(float& lo, float& hi, u64 u) {
    asm("mov.b64 {%0, %1}, %2;" : "=f"(lo), "=f"(hi) : "l"(u));
}

// ---------- mma helpers ----------
__device__ __forceinline__ u32 smem_u32(const void* p) {
    u32 a; asm("{ .reg .u64 t; cvta.to.shared.u64 t, %1; cvt.u32.u64 %0, t; }"
               : "=r"(a) : "l"(p));
    return a;
}
__device__ __forceinline__ void ldsmT(u32& r0, u32& r1, u32 addr) {
    asm volatile("ldmatrix.sync.aligned.m8n8.x2.trans.shared.b16 {%0,%1}, [%2];"
                 : "=r"(r0), "=r"(r1) : "r"(addr));
}
__device__ __forceinline__ void mma16816(float* d, const u32* a, u32 b0, u32 b1) {
    asm volatile("mma.sync.aligned.m16n8k16.row.col.f32.f16.f16.f32 "
        "{%0,%1,%2,%3}, {%4,%5,%6,%7}, {%8,%9}, {%0,%1,%2,%3};"
        : "+f"(d[0]), "+f"(d[1]), "+f"(d[2]), "+f"(d[3])
        : "r"(a[0]), "r"(a[1]), "r"(a[2]), "r"(a[3]), "r"(b0), "r"(b1));
}
// split (x,y) -> fp16x2 hi + fp16x2 lo (residual)
__device__ __forceinline__ void sp2(float x, float y, u32& h, u32& l) {
    __half2 hh = __floats2half2_rn(x, y);
    float2 r = __half22float2(hh);
    __half2 ll = __floats2half2_rn(x - r.x, y - r.y);
    h = *(u32*)&hh; l = *(u32*)&ll;
}
// register-resident A fragments (m16n8k16 row-major layout) from gmem W[n][128]
__device__ __forceinline__ void loadA(const float* W, int n0, int lane,
                                      u32 ah[8][4], u32 al[8][4]) {
    const int r = lane >> 2, c = 2 * (lane & 3);
    #pragma unroll
    for (int ks = 0; ks < 8; ks++)
        #pragma unroll
        for (int q = 0; q < 4; q++) {
            const int rr = n0 + r + (q & 1) * 8;
            const int cc = 16 * ks + c + (q >> 1) * 8;
            const float2 p = *(const float2*)&W[rr * 128 + cc];
            sp2(p.x, p.y, ah[ks][q], al[ks][q]);
        }
}
// stage fp32 [128][128] -> smem fp16 hi/lo tiles
__device__ __forceinline__ void stage(const float* src, __half* sHh, __half* sHl,
                                      int tid, int nthr) {
    for (int i = tid; i < HDIM * 64; i += nthr) {
        const int k = i >> 6, b2 = (i & 63) * 2;
        const float2 p = *(const float2*)&src[k * BDIM + b2];
        u32 h, l; sp2(p.x, p.y, h, l);
        *(u32*)&sHh[k * SHS + b2] = h;
        *(u32*)&sHl[k * SHS + b2] = l;
    }
}

// ---------------- Ksq ----------------
__global__ __launch_bounds__(128, 1)
void k_sq(const float* __restrict__ src, float* __restrict__ dst)
{
    __shared__ float row[HDIM];
    const int r = blockIdx.x, c = threadIdx.x;
    row[c] = src[r * HDIM + c];
    __syncthreads();
    float a0 = 0, a1 = 0, a2 = 0, a3 = 0;
    #pragma unroll 8
    for (int k = 0; k < HDIM; k += 4) {
        a0 = fmaf(row[k],     src[(k)     * HDIM + c], a0);
        a1 = fmaf(row[k + 1], src[(k + 1) * HDIM + c], a1);
        a2 = fmaf(row[k + 2], src[(k + 2) * HDIM + c], a2);
        a3 = fmaf(row[k + 3], src[(k + 3) * HDIM + c], a3);
    }
    dst[r * HDIM + c] = (a0 + a1) + (a2 + a3);
}

// ---------------- K1 (SIMT, unchanged) ----------------
__global__ __launch_bounds__(256, 1)
void k1_ux(const float* __restrict__ x,
           const float* __restrict__ A3,
           const float* __restrict__ A1)
{
    extern __shared__ float sm[];
    float* sWt = sm;
    float* sX  = sm + 64 * 192;
    const int tid = threadIdx.x;

    for (int idx = tid; idx < 192 * 64; idx += 256) {
        const int r = idx / 64, kk = idx % 64;
        sWt[kk * 192 + r] = (r < HDIM) ? A3[r * KDIM + kk]
                                       : A1[(r - HDIM) * KDIM + kk];
    }
    {
        const float4* xg = (const float4*)(x + (size_t)blockIdx.x * KDIM * BDIM);
        float4* s0 = (float4*)sX;
        for (int idx = tid; idx < 2048; idx += 256) s0[idx] = xg[idx];
    }
    __syncthreads();

    const int ty = tid >> 4, tx = tid & 15;
    const int r0 = ty * 12, c0 = tx * 8;

    int it = 0;
    #pragma unroll 1
    for (int t = blockIdx.x; t < T_STEPS; t += K1_GRID, it ^= 1) {
        const int tn = t + K1_GRID;
        if (tn < T_STEPS) {
            const float4* xg = (const float4*)(x + (size_t)tn * KDIM * BDIM);
            float4* sn = (float4*)(sX + (it ^ 1) * 8192);
            for (int idx = tid; idx < 2048; idx += 256) sn[idx] = xg[idx];
        }
        const float* sXc = sX + it * 8192;

        u64 acc[12][4];
        #pragma unroll
        for (int m = 0; m < 12; m++)
            #pragma unroll
            for (int j = 0; j < 4; j++) acc[m][j] = 0ull;

        #pragma unroll 2
        for (int kk = 0; kk < 64; kk++) {
            const float4 w0 = *(const float4*)&sWt[kk * 192 + r0];
            const float4 w1 = *(const float4*)&sWt[kk * 192 + r0 + 4];
            const float4 w2 = *(const float4*)&sWt[kk * 192 + r0 + 8];
            const ulonglong2 xa = *(const ulonglong2*)&sXc[kk * 128 + c0];
            const ulonglong2 xb = *(const ulonglong2*)&sXc[kk * 128 + c0 + 4];
            const u64 xv[4] = {xa.x, xa.y, xb.x, xb.y};
            const float wv[12] = {w0.x, w0.y, w0.z, w0.w,
                                  w1.x, w1.y, w1.z, w1.w,
                                  w2.x, w2.y, w2.z, w2.w};
            #pragma unroll
            for (int m = 0; m < 12; m++) {
                const u64 ws = pk2s(wv[m]);
                #pragma unroll
                for (int j = 0; j < 4; j++)
                    acc[m][j] = ffma2(ws, xv[j], acc[m][j]);
            }
        }
        #pragma unroll
        for (int m = 0; m < 12; m++) {
            float* dst = &g_UZ[((size_t)t * 192 + r0 + m) * BDIM + c0];
            *(ulonglong2*)dst       = make_ulonglong2(acc[m][0], acc[m][1]);
            *((ulonglong2*)dst + 1) = make_ulonglong2(acc[m][2], acc[m][3]);
        }
        __syncthreads();
    }
}

// ---------------- K3 (SIMT, unchanged) ----------------
__global__ __launch_bounds__(128, 1)
void k3_scan(const float* __restrict__ h0)
{
    extern __shared__ float sm[];
    float* sP = sm;
    float* sS = sm + 128 * 130;
    const int b = blockIdx.x;
    const int tid = threadIdx.x;

    for (int idx = tid; idx < 128 * 128; idx += 128) {
        const int r = idx >> 7, kk = idx & 127;
        sP[r * 130 + kk] = g_Pa[idx];
    }
    float s = h0[tid * BDIM + b];
    sS[tid] = s;
    __syncthreads();

    #pragma unroll 1
    for (int i = 0; i < NCHUNK; i++) {
        g_S[((size_t)i * HDIM + tid) * BDIM + b] = s;
        const float w = g_W[((size_t)i * HDIM + tid) * BDIM + b];
        const u64* s2 = (const u64*)sS;
        const u64* p2 = (const u64*)&sP[tid * 130];
        u64 a0 = 0ull, a1 = 0ull, a2 = 0ull, a3 = 0ull;
        #pragma unroll 4
        for (int m = 0; m < 64; m += 4) {
            a0 = ffma2(p2[m],     s2[m],     a0);
            a1 = ffma2(p2[m + 1], s2[m + 1], a1);
            a2 = ffma2(p2[m + 2], s2[m + 2], a2);
            a3 = ffma2(p2[m + 3], s2[m + 3], a3);
        }
        const u64 aa = fadd2(fadd2(a0, a1), fadd2(a2, a3));
        float lo, hi; upk2(lo, hi, aa);
        s = lo + hi + w;
        __syncthreads();
        sS[tid] = s;
        __syncthreads();
    }
}

// ---------------- k_rec: HMMA chunk recurrence ----------------
// mode 0: state=u_{t0}, steps 1..31, write g_W at last step
// mode 1: state=g_S[ic], steps 0..31, write out_hidden each step
__global__ __launch_bounds__(256, 1)
void k_rec(const int mode, const float* __restrict__ A4w,
           float* __restrict__ out_hidden)
{
    extern __shared__ __align__(16) __half sh[];
    __half* sHh = sh;
    __half* sHl = sh + HDIM * SHS;

    const int ic  = blockIdx.x;
    const int tid = threadIdx.x;
    const int w = tid >> 5, lane = tid & 31;
    const int n0 = w * 16;
    const int r = lane >> 2, c = 2 * (lane & 3);

    u32 ah[8][4], al[8][4];
    loadA(A4w, n0, lane, ah, al);

    stage(mode ? g_S + (size_t)ic * HDIM * BDIM
               : g_UZ + (size_t)(ic * CHUNK) * 192 * BDIM,
          sHh, sHl, tid, 256);
    __syncthreads();

    const u32 bH = smem_u32(sHh), bL = smem_u32(sHl);

    #pragma unroll 1
    for (int cc = (mode ? 0 : 1); cc < CHUNK; cc++) {
        const int t = ic * CHUNK + cc;

        // accumulators initialized from u_t
        float d[16][4];
        const float* u = g_UZ + (size_t)t * 192 * BDIM;
        #pragma unroll
        for (int bt = 0; bt < 16; bt++) {
            const float2 p0 = *(const float2*)&u[(n0 + r) * BDIM + 8 * bt + c];
            const float2 p1 = *(const float2*)&u[(n0 + r + 8) * BDIM + 8 * bt + c];
            d[bt][0] = p0.x; d[bt][1] = p0.y; d[bt][2] = p1.x; d[bt][3] = p1.y;
        }

        #pragma unroll
        for (int ks = 0; ks < 8; ks++) {
            const u32 ad = (u32)((16 * ks + (lane & 15)) * SHS) * 2;
            #pragma unroll
            for (int bt = 0; bt < 16; bt++) {
                u32 bh0, bh1, bl0, bl1;
                ldsmT(bh0, bh1, bH + ad + 16 * bt);
                ldsmT(bl0, bl1, bL + ad + 16 * bt);
                mma16816(d[bt], ah[ks], bh0, bh1);
                mma16816(d[bt], ah[ks], bl0, bl1);
                mma16816(d[bt], al[ks], bh0, bh1);
            }
        }
        __syncthreads();   // all warps done reading old state

        const bool wr = mode || (cc == CHUNK - 1);
        float* go = mode ? out_hidden + (size_t)t * HDIM * BDIM
                         : g_W + (size_t)ic * HDIM * BDIM;
        #pragma unroll
        for (int bt = 0; bt < 16; bt++) {
            if (cc < CHUNK - 1) {
                u32 h0, l0, h1, l1;
                sp2(d[bt][0], d[bt][1], h0, l0);
                sp2(d[bt][2], d[bt][3], h1, l1);
                *(u32*)&sHh[(n0 + r) * SHS + 8 * bt + c]     = h0;
                *(u32*)&sHl[(n0 + r) * SHS + 8 * bt + c]     = l0;
                *(u32*)&sHh[(n0 + r + 8) * SHS + 8 * bt + c] = h1;
                *(u32*)&sHl[(n0 + r + 8) * SHS + 8 * bt + c] = l1;
            }
            if (wr) {
                *(float2*)&go[(n0 + r) * BDIM + 8 * bt + c]     = make_float2(d[bt][0], d[bt][1]);
                *(float2*)&go[(n0 + r + 8) * BDIM + 8 * bt + c] = make_float2(d[bt][2], d[bt][3]);
            }
        }
        __syncthreads();   // new state visible
    }
}

// ---------------- k5: known_t = Z_t + A2 h_{t-1} (HMMA, parallel) ----------------
__global__ __launch_bounds__(128, 1)
void k5_known(const float* __restrict__ A2w,
              const float* __restrict__ out_hidden,
              float* __restrict__ out_known)
{
    extern __shared__ __align__(16) __half sh[];
    __half* sHh = sh;
    __half* sHl = sh + HDIM * SHS;

    const int t   = blockIdx.x;
    const int tid = threadIdx.x;
    const int w = tid >> 5, lane = tid & 31;
    const int n0 = w * 16;                 // known rows (64 total over 4 warps)
    const int r = lane >> 2, c = 2 * (lane & 3);

    u32 ah[8][4], al[8][4];
    loadA(A2w, n0, lane, ah, al);

    const float* hsrc = (t % CHUNK == 0)
        ? g_S + (size_t)(t / CHUNK) * HDIM * BDIM
        : out_hidden + (size_t)(t - 1) * HDIM * BDIM;
    stage(hsrc, sHh, sHl, tid, 128);
    __syncthreads();

    const u32 bH = smem_u32(sHh), bL = smem_u32(sHl);

    float d[16][4];
    const float* z = g_UZ + ((size_t)t * 192 + 128) * BDIM;
    #pragma unroll
    for (int bt = 0; bt < 16; bt++) {
        const float2 p0 = *(const float2*)&z[(n0 + r) * BDIM + 8 * bt + c];
        const float2 p1 = *(const float2*)&z[(n0 + r + 8) * BDIM + 8 * bt + c];
        d[bt][0] = p0.x; d[bt][1] = p0.y; d[bt][2] = p1.x; d[bt][3] = p1.y;
    }
    #pragma unroll
    for (int ks = 0; ks < 8; ks++) {
        const u32 ad = (u32)((16 * ks + (lane & 15)) * SHS) * 2;
        #pragma unroll
        for (int bt = 0; bt < 16; bt++) {
            u32 bh0, bh1, bl0, bl1;
            ldsmT(bh0, bh1, bH + ad + 16 * bt);
            ldsmT(bl0, bl1, bL + ad + 16 * bt);
            mma16816(d[bt], ah[ks], bh0, bh1);
            mma16816(d[bt], ah[ks], bl0, bl1);
            mma16816(d[bt], al[ks], bh0, bh1);
        }
    }
    float* go = out_known + (size_t)t * KDIM * BDIM;
    #pragma unroll
    for (int bt = 0; bt < 16; bt++) {
        *(float2*)&go[(n0 + r) * BDIM + 8 * bt + c]     = make_float2(d[bt][0], d[bt][1]);
        *(float2*)&go[(n0 + r + 8) * BDIM + 8 * bt + c] = make_float2(d[bt][2], d[bt][3]);
    }
}

// ---------------- host ----------------
extern "C" void kernel_launch(void* const* d_in, const int* in_sizes, int n_in,
                              void* d_out, int out_size)
{
    const float* x  = (const float*)d_in[0];
    const float* h0 = (const float*)d_in[1];
    const float* A1 = (const float*)d_in[2];
    const float* A2 = (const float*)d_in[3];
    const float* A3 = (const float*)d_in[4];
    const float* A4 = (const float*)d_in[5];

    float* out_known  = (float*)d_out;
    float* out_hidden = (float*)d_out + (size_t)T_STEPS * KDIM * BDIM;

    const int smem1 = (64 * 192 + 2 * 64 * 128) * 4;   // 114688
    const int smem3 = (128 * 130 + 128) * 4;           // 67072
    const int smemR = 2 * HDIM * SHS * 2;              // 69632

    cudaFuncSetAttribute(k1_ux,   cudaFuncAttributeMaxDynamicSharedMemorySize, smem1);
    cudaFuncSetAttribute(k3_scan, cudaFuncAttributeMaxDynamicSharedMemorySize, smem3);
    cudaFuncSetAttribute(k_rec,   cudaFuncAttributeMaxDynamicSharedMemorySize, smemR);
    cudaFuncSetAttribute(k5_known,cudaFuncAttributeMaxDynamicSharedMemorySize, smemR);

    float *pa, *pb;
    cudaGetSymbolAddress((void**)&pa, g_Pa);
    cudaGetSymbolAddress((void**)&pb, g_Pb);

    k_sq<<<HDIM, HDIM>>>(A4, pa);   // A4^2
    k_sq<<<HDIM, HDIM>>>(pa, pb);   // A4^4
    k_sq<<<HDIM, HDIM>>>(pb, pa);   // A4^8
    k_sq<<<HDIM, HDIM>>>(pa, pb);   // A4^16
    k_sq<<<HDIM, HDIM>>>(pb, pa);   // A4^32 -> g_Pa

    k1_ux<<<K1_GRID, 256, smem1>>>(x, A3, A1);
    k_rec<<<NCHUNK, 256, smemR>>>(0, A4, nullptr);
    k3_scan<<<BDIM, 128, smem3>>>(h0);
    k_rec<<<NCHUNK, 256, smemR>>>(1, A4, out_hidden);
    k5_known<<<T_STEPS, 128, smemR>>>(A2, out_hidden, out_known);

    (void)in_sizes; (void)n_in; (void)out_size;
}

// round 12
// speedup vs baseline: 1.9483x; 1.2116x over previous
#include <cuda_runtime.h>
#include <cuda_fp16.h>

// CustomLinearRNN via chunked parallel scan; all GEMM phases on mma.sync HMMA
// with fp16 hi/lo 3-term split (error ~2^-22).
//  k_pow  : P = A4^32, single CTA, 5 in-kernel squarings (HMMA)
//  k1     : UZ[t] = [A3;A1] x_t (HMMA, persistent grid 148)
//  k_rec(0): zero-state chunk scan -> g_W (HMMA)
//  k3     : boundary scan s_{i+1} = P s_i + W_i (fp32 SIMT)
//  k_rec(1): rerun chunks from g_S -> out_hidden (HMMA)
//  k5     : known_t = Z_t + A2 h_{t-1} (HMMA, parallel over t)

#define T_STEPS 4096
#define KDIM 64
#define HDIM 128
#define BDIM 128
#define CHUNK 32
#define NCHUNK 128
#define K1_GRID 148
#define SHS 136   // fp16 smem row stride (16B aligned, conflict-free)

typedef unsigned long long u64;
typedef unsigned int u32;

__device__ float g_UZ[(size_t)T_STEPS * 192 * BDIM];
__device__ float g_W[(size_t)NCHUNK * HDIM * BDIM];
__device__ float g_S[(size_t)NCHUNK * HDIM * BDIM];
__device__ float g_Pa[HDIM * HDIM];

// ---------- SIMT helpers ----------
__device__ __forceinline__ u64 ffma2(u64 a, u64 b, u64 c) {
    u64 d; asm("fma.rn.f32x2 %0, %1, %2, %3;" : "=l"(d) : "l"(a), "l"(b), "l"(c));
    return d;
}
__device__ __forceinline__ u64 fadd2(u64 a, u64 b) {
    u64 d; asm("add.rn.f32x2 %0, %1, %2;" : "=l"(d) : "l"(a), "l"(b));
    return d;
}
__device__ __forceinline__ void upk2(float& lo, float& hi, u64 u) {
    asm("mov.b64 {%0, %1}, %2;" : "=f"(lo), "=f"(hi) : "l"(u));
}

// ---------- mma helpers ----------
__device__ __forceinline__ u32 smem_u32(const void* p) {
    u32 a; asm("{ .reg .u64 t; cvta.to.shared.u64 t, %1; cvt.u32.u64 %0, t; }"
               : "=r"(a) : "l"(p));
    return a;
}
__device__ __forceinline__ void ldsmT(u32& r0, u32& r1, u32 addr) {
    asm volatile("ldmatrix.sync.aligned.m8n8.x2.trans.shared.b16 {%0,%1}, [%2];"
                 : "=r"(r0), "=r"(r1) : "r"(addr));
}
__device__ __forceinline__ void mma16816(float* d, const u32* a, u32 b0, u32 b1) {
    asm volatile("mma.sync.aligned.m16n8k16.row.col.f32.f16.f16.f32 "
        "{%0,%1,%2,%3}, {%4,%5,%6,%7}, {%8,%9}, {%0,%1,%2,%3};"
        : "+f"(d[0]), "+f"(d[1]), "+f"(d[2]), "+f"(d[3])
        : "r"(a[0]), "r"(a[1]), "r"(a[2]), "r"(a[3]), "r"(b0), "r"(b1));
}
__device__ __forceinline__ void sp2(float x, float y, u32& h, u32& l) {
    __half2 hh = __floats2half2_rn(x, y);
    float2 r = __half22float2(hh);
    __half2 ll = __floats2half2_rn(x - r.x, y - r.y);
    h = *(u32*)&hh; l = *(u32*)&ll;
}
// A fragments from gmem W[n][128] (K=128)
__device__ __forceinline__ void loadA(const float* W, int n0, int lane,
                                      u32 ah[8][4], u32 al[8][4]) {
    const int r = lane >> 2, c = 2 * (lane & 3);
    #pragma unroll
    for (int ks = 0; ks < 8; ks++)
        #pragma unroll
        for (int q = 0; q < 4; q++) {
            const int rr = n0 + r + (q & 1) * 8;
            const int cc = 16 * ks + c + (q >> 1) * 8;
            const float2 p = *(const float2*)&W[rr * 128 + cc];
            sp2(p.x, p.y, ah[ks][q], al[ks][q]);
        }
}
// stage fp32 [128][128] -> smem fp16 hi/lo
__device__ __forceinline__ void stage(const float* src, __half* sHh, __half* sHl,
                                      int tid, int nthr) {
    for (int i = tid; i < HDIM * 64; i += nthr) {
        const int k = i >> 6, b2 = (i & 63) * 2;
        const float2 p = *(const float2*)&src[k * BDIM + b2];
        u32 h, l; sp2(p.x, p.y, h, l);
        *(u32*)&sHh[k * SHS + b2] = h;
        *(u32*)&sHl[k * SHS + b2] = l;
    }
}

// ---------------- k_pow: P = A4^32, single CTA, HMMA ----------------
__global__ __launch_bounds__(256, 1)
void k_pow(const float* __restrict__ A4)
{
    extern __shared__ __align__(16) __half sh[];
    // [buf][hi/lo][128*SHS]
    __half* tiles = sh;
    const int tid = threadIdx.x;
    const int w = tid >> 5, lane = tid & 31;
    const int n0 = w * 16;
    const int r = lane >> 2, c = 2 * (lane & 3);

    stage(A4, tiles, tiles + HDIM * SHS, tid, 256);
    __syncthreads();

    #pragma unroll 1
    for (int iter = 0; iter < 5; iter++) {
        __half* curH = tiles + (iter & 1) * 2 * HDIM * SHS;
        __half* curL = curH + HDIM * SHS;
        __half* nxtH = tiles + ((iter + 1) & 1) * 2 * HDIM * SHS;
        __half* nxtL = nxtH + HDIM * SHS;

        // A fragments reconstructed from hi+lo tiles
        u32 ah[8][4], al[8][4];
        #pragma unroll
        for (int ks = 0; ks < 8; ks++)
            #pragma unroll
            for (int q = 0; q < 4; q++) {
                const int rr = n0 + r + (q & 1) * 8;
                const int cc = 16 * ks + c + (q >> 1) * 8;
                const u32 ph = *(u32*)&curH[rr * SHS + cc];
                const u32 pl = *(u32*)&curL[rr * SHS + cc];
                const float2 fh = __half22float2(*(__half2*)&ph);
                const float2 fl = __half22float2(*(__half2*)&pl);
                sp2(fh.x + fl.x, fh.y + fl.y, ah[ks][q], al[ks][q]);
            }

        const u32 bH = smem_u32(curH), bL = smem_u32(curL);
        float d[16][4];
        #pragma unroll
        for (int bt = 0; bt < 16; bt++)
            d[bt][0] = d[bt][1] = d[bt][2] = d[bt][3] = 0.f;

        #pragma unroll
        for (int ks = 0; ks < 8; ks++) {
            const u32 ad = (u32)((16 * ks + (lane & 15)) * SHS) * 2;
            #pragma unroll
            for (int bt = 0; bt < 16; bt++) {
                u32 bh0, bh1, bl0, bl1;
                ldsmT(bh0, bh1, bH + ad + 16 * bt);
                ldsmT(bl0, bl1, bL + ad + 16 * bt);
                mma16816(d[bt], ah[ks], bh0, bh1);
                mma16816(d[bt], ah[ks], bl0, bl1);
                mma16816(d[bt], al[ks], bh0, bh1);
            }
        }
        __syncthreads();
        #pragma unroll
        for (int bt = 0; bt < 16; bt++) {
            u32 h0, l0, h1, l1;
            sp2(d[bt][0], d[bt][1], h0, l0);
            sp2(d[bt][2], d[bt][3], h1, l1);
            *(u32*)&nxtH[(n0 + r) * SHS + 8 * bt + c]     = h0;
            *(u32*)&nxtL[(n0 + r) * SHS + 8 * bt + c]     = l0;
            *(u32*)&nxtH[(n0 + r + 8) * SHS + 8 * bt + c] = h1;
            *(u32*)&nxtL[(n0 + r + 8) * SHS + 8 * bt + c] = l1;
            if (iter == 4) {
                *(float2*)&g_Pa[(n0 + r) * HDIM + 8 * bt + c]     = make_float2(d[bt][0], d[bt][1]);
                *(float2*)&g_Pa[(n0 + r + 8) * HDIM + 8 * bt + c] = make_float2(d[bt][2], d[bt][3]);
            }
        }
        __syncthreads();
    }
}

// ---------------- k1: UZ = [A3;A1] x_t  (HMMA, persistent) ----------------
__global__ __launch_bounds__(384, 1)
void k1_ux(const float* __restrict__ x,
           const float* __restrict__ A3,
           const float* __restrict__ A1)
{
    extern __shared__ __align__(16) __half sh[];
    // [buf][hi/lo][64*SHS]
    const int tid = threadIdx.x;
    const int w = tid >> 5, lane = tid & 31;
    const int n0 = w * 16;                  // 0..176
    const int r = lane >> 2, c = 2 * (lane & 3);

    // A fragments: stacked [A3;A1], K=64
    u32 ah[4][4], al[4][4];
    #pragma unroll
    for (int ks = 0; ks < 4; ks++)
        #pragma unroll
        for (int q = 0; q < 4; q++) {
            const int rr = n0 + r + (q & 1) * 8;
            const int cc = 16 * ks + c + (q >> 1) * 8;
            const float2 p = (rr < HDIM)
                ? *(const float2*)&A3[rr * KDIM + cc]
                : *(const float2*)&A1[(rr - HDIM) * KDIM + cc];
            sp2(p.x, p.y, ah[ks][q], al[ks][q]);
        }

    // preload first x tile into buf 0
    {
        const float* src = x + (size_t)blockIdx.x * KDIM * BDIM;
        for (int i = tid; i < KDIM * 64; i += 384) {
            const int k = i >> 6, b2 = (i & 63) * 2;
            const float2 p = *(const float2*)&src[k * BDIM + b2];
            u32 h, l; sp2(p.x, p.y, h, l);
            *(u32*)&sh[k * SHS + b2]              = h;
            *(u32*)&sh[KDIM * SHS + k * SHS + b2] = l;
        }
    }

    int buf = 0;
    #pragma unroll 1
    for (int t = blockIdx.x; t < T_STEPS; t += K1_GRID, buf ^= 1) {
        __syncthreads();   // current buf staged; previous mma reads done
        // stage t+grid into other buffer (latency hides under mma)
        const int tn = t + K1_GRID;
        if (tn < T_STEPS) {
            const float* src = x + (size_t)tn * KDIM * BDIM;
            __half* dH = sh + (buf ^ 1) * 2 * KDIM * SHS;
            __half* dL = dH + KDIM * SHS;
            for (int i = tid; i < KDIM * 64; i += 384) {
                const int k = i >> 6, b2 = (i & 63) * 2;
                const float2 p = *(const float2*)&src[k * BDIM + b2];
                u32 h, l; sp2(p.x, p.y, h, l);
                *(u32*)&dH[k * SHS + b2] = h;
                *(u32*)&dL[k * SHS + b2] = l;
            }
        }

        const u32 bH = smem_u32(sh + buf * 2 * KDIM * SHS);
        const u32 bL = bH + KDIM * SHS * 2;

        float d[16][4];
        #pragma unroll
        for (int bt = 0; bt < 16; bt++)
            d[bt][0] = d[bt][1] = d[bt][2] = d[bt][3] = 0.f;

        #pragma unroll
        for (int ks = 0; ks < 4; ks++) {
            const u32 ad = (u32)((16 * ks + (lane & 15)) * SHS) * 2;
            #pragma unroll
            for (int bt = 0; bt < 16; bt++) {
                u32 bh0, bh1, bl0, bl1;
                ldsmT(bh0, bh1, bH + ad + 16 * bt);
                ldsmT(bl0, bl1, bL + ad + 16 * bt);
                mma16816(d[bt], ah[ks], bh0, bh1);
                mma16816(d[bt], ah[ks], bl0, bl1);
                mma16816(d[bt], al[ks], bh0, bh1);
            }
        }
        float* go = g_UZ + (size_t)t * 192 * BDIM;
        #pragma unroll
        for (int bt = 0; bt < 16; bt++) {
            *(float2*)&go[(n0 + r) * BDIM + 8 * bt + c]     = make_float2(d[bt][0], d[bt][1]);
            *(float2*)&go[(n0 + r + 8) * BDIM + 8 * bt + c] = make_float2(d[bt][2], d[bt][3]);
        }
    }
}

// ---------------- k3: boundary scan (SIMT, unchanged) ----------------
__global__ __launch_bounds__(128, 1)
void k3_scan(const float* __restrict__ h0)
{
    extern __shared__ float sm[];
    float* sP = sm;
    float* sS = sm + 128 * 130;
    const int b = blockIdx.x;
    const int tid = threadIdx.x;

    for (int idx = tid; idx < 128 * 128; idx += 128) {
        const int r = idx >> 7, kk = idx & 127;
        sP[r * 130 + kk] = g_Pa[idx];
    }
    float s = h0[tid * BDIM + b];
    sS[tid] = s;
    __syncthreads();

    #pragma unroll 1
    for (int i = 0; i < NCHUNK; i++) {
        g_S[((size_t)i * HDIM + tid) * BDIM + b] = s;
        const float w = g_W[((size_t)i * HDIM + tid) * BDIM + b];
        const u64* s2 = (const u64*)sS;
        const u64* p2 = (const u64*)&sP[tid * 130];
        u64 a0 = 0ull, a1 = 0ull, a2 = 0ull, a3 = 0ull;
        #pragma unroll 4
        for (int m = 0; m < 64; m += 4) {
            a0 = ffma2(p2[m],     s2[m],     a0);
            a1 = ffma2(p2[m + 1], s2[m + 1], a1);
            a2 = ffma2(p2[m + 2], s2[m + 2], a2);
            a3 = ffma2(p2[m + 3], s2[m + 3], a3);
        }
        const u64 aa = fadd2(fadd2(a0, a1), fadd2(a2, a3));
        float lo, hi; upk2(lo, hi, aa);
        s = lo + hi + w;
        __syncthreads();
        sS[tid] = s;
        __syncthreads();
    }
}

// ---------------- k_rec: HMMA chunk recurrence (unchanged) ----------------
__global__ __launch_bounds__(256, 1)
void k_rec(const int mode, const float* __restrict__ A4w,
           float* __restrict__ out_hidden)
{
    extern __shared__ __align__(16) __half sh[];
    __half* sHh = sh;
    __half* sHl = sh + HDIM * SHS;

    const int ic  = blockIdx.x;
    const int tid = threadIdx.x;
    const int w = tid >> 5, lane = tid & 31;
    const int n0 = w * 16;
    const int r = lane >> 2, c = 2 * (lane & 3);

    u32 ah[8][4], al[8][4];
    loadA(A4w, n0, lane, ah, al);

    stage(mode ? g_S + (size_t)ic * HDIM * BDIM
               : g_UZ + (size_t)(ic * CHUNK) * 192 * BDIM,
          sHh, sHl, tid, 256);
    __syncthreads();

    const u32 bH = smem_u32(sHh), bL = smem_u32(sHl);

    #pragma unroll 1
    for (int cc = (mode ? 0 : 1); cc < CHUNK; cc++) {
        const int t = ic * CHUNK + cc;

        float d[16][4];
        const float* u = g_UZ + (size_t)t * 192 * BDIM;
        #pragma unroll
        for (int bt = 0; bt < 16; bt++) {
            const float2 p0 = *(const float2*)&u[(n0 + r) * BDIM + 8 * bt + c];
            const float2 p1 = *(const float2*)&u[(n0 + r + 8) * BDIM + 8 * bt + c];
            d[bt][0] = p0.x; d[bt][1] = p0.y; d[bt][2] = p1.x; d[bt][3] = p1.y;
        }

        #pragma unroll
        for (int ks = 0; ks < 8; ks++) {
            const u32 ad = (u32)((16 * ks + (lane & 15)) * SHS) * 2;
            #pragma unroll
            for (int bt = 0; bt < 16; bt++) {
                u32 bh0, bh1, bl0, bl1;
                ldsmT(bh0, bh1, bH + ad + 16 * bt);
                ldsmT(bl0, bl1, bL + ad + 16 * bt);
                mma16816(d[bt], ah[ks], bh0, bh1);
                mma16816(d[bt], ah[ks], bl0, bl1);
                mma16816(d[bt], al[ks], bh0, bh1);
            }
        }
        __syncthreads();

        const bool wr = mode || (cc == CHUNK - 1);
        float* go = mode ? out_hidden + (size_t)t * HDIM * BDIM
                         : g_W + (size_t)ic * HDIM * BDIM;
        #pragma unroll
        for (int bt = 0; bt < 16; bt++) {
            if (cc < CHUNK - 1) {
                u32 h0, l0, h1, l1;
                sp2(d[bt][0], d[bt][1], h0, l0);
                sp2(d[bt][2], d[bt][3], h1, l1);
                *(u32*)&sHh[(n0 + r) * SHS + 8 * bt + c]     = h0;
                *(u32*)&sHl[(n0 + r) * SHS + 8 * bt + c]     = l0;
                *(u32*)&sHh[(n0 + r + 8) * SHS + 8 * bt + c] = h1;
                *(u32*)&sHl[(n0 + r + 8) * SHS + 8 * bt + c] = l1;
            }
            if (wr) {
                *(float2*)&go[(n0 + r) * BDIM + 8 * bt + c]     = make_float2(d[bt][0], d[bt][1]);
                *(float2*)&go[(n0 + r + 8) * BDIM + 8 * bt + c] = make_float2(d[bt][2], d[bt][3]);
            }
        }
        __syncthreads();
    }
}

// ---------------- k5: known_t = Z_t + A2 h_{t-1} (unchanged) ----------------
__global__ __launch_bounds__(128, 1)
void k5_known(const float* __restrict__ A2w,
              const float* __restrict__ out_hidden,
              float* __restrict__ out_known)
{
    extern __shared__ __align__(16) __half sh[];
    __half* sHh = sh;
    __half* sHl = sh + HDIM * SHS;

    const int t   = blockIdx.x;
    const int tid = threadIdx.x;
    const int w = tid >> 5, lane = tid & 31;
    const int n0 = w * 16;
    const int r = lane >> 2, c = 2 * (lane & 3);

    u32 ah[8][4], al[8][4];
    loadA(A2w, n0, lane, ah, al);

    const float* hsrc = (t % CHUNK == 0)
        ? g_S + (size_t)(t / CHUNK) * HDIM * BDIM
        : out_hidden + (size_t)(t - 1) * HDIM * BDIM;
    stage(hsrc, sHh, sHl, tid, 128);
    __syncthreads();

    const u32 bH = smem_u32(sHh), bL = smem_u32(sHl);

    float d[16][4];
    const float* z = g_UZ + ((size_t)t * 192 + 128) * BDIM;
    #pragma unroll
    for (int bt = 0; bt < 16; bt++) {
        const float2 p0 = *(const float2*)&z[(n0 + r) * BDIM + 8 * bt + c];
        const float2 p1 = *(const float2*)&z[(n0 + r + 8) * BDIM + 8 * bt + c];
        d[bt][0] = p0.x; d[bt][1] = p0.y; d[bt][2] = p1.x; d[bt][3] = p1.y;
    }
    #pragma unroll
    for (int ks = 0; ks < 8; ks++) {
        const u32 ad = (u32)((16 * ks + (lane & 15)) * SHS) * 2;
        #pragma unroll
        for (int bt = 0; bt < 16; bt++) {
            u32 bh0, bh1, bl0, bl1;
            ldsmT(bh0, bh1, bH + ad + 16 * bt);
            ldsmT(bl0, bl1, bL + ad + 16 * bt);
            mma16816(d[bt], ah[ks], bh0, bh1);
            mma16816(d[bt], ah[ks], bl0, bl1);
            mma16816(d[bt], al[ks], bh0, bh1);
        }
    }
    float* go = out_known + (size_t)t * KDIM * BDIM;
    #pragma unroll
    for (int bt = 0; bt < 16; bt++) {
        *(float2*)&go[(n0 + r) * BDIM + 8 * bt + c]     = make_float2(d[bt][0], d[bt][1]);
        *(float2*)&go[(n0 + r + 8) * BDIM + 8 * bt + c] = make_float2(d[bt][2], d[bt][3]);
    }
}

// ---------------- host ----------------
extern "C" void kernel_launch(void* const* d_in, const int* in_sizes, int n_in,
                              void* d_out, int out_size)
{
    const float* x  = (const float*)d_in[0];
    const float* h0 = (const float*)d_in[1];
    const float* A1 = (const float*)d_in[2];
    const float* A2 = (const float*)d_in[3];
    const float* A3 = (const float*)d_in[4];
    const float* A4 = (const float*)d_in[5];

    float* out_known  = (float*)d_out;
    float* out_hidden = (float*)d_out + (size_t)T_STEPS * KDIM * BDIM;

    const int smemP = 2 * 2 * HDIM * SHS * 2;   // 139264 (k_pow: 2 bufs hi/lo)
    const int smem1 = 2 * 2 * KDIM * SHS * 2;   // 69632  (k1: 2 bufs hi/lo)
    const int smem3 = (128 * 130 + 128) * 4;    // 67072
    const int smemR = 2 * HDIM * SHS * 2;       // 69632

    cudaFuncSetAttribute(k_pow,   cudaFuncAttributeMaxDynamicSharedMemorySize, smemP);
    cudaFuncSetAttribute(k1_ux,   cudaFuncAttributeMaxDynamicSharedMemorySize, smem1);
    cudaFuncSetAttribute(k3_scan, cudaFuncAttributeMaxDynamicSharedMemorySize, smem3);
    cudaFuncSetAttribute(k_rec,   cudaFuncAttributeMaxDynamicSharedMemorySize, smemR);
    cudaFuncSetAttribute(k5_known,cudaFuncAttributeMaxDynamicSharedMemorySize, smemR);

    k_pow<<<1, 256, smemP>>>(A4);
    k1_ux<<<K1_GRID, 384, smem1>>>(x, A3, A1);
    k_rec<<<NCHUNK, 256, smemR>>>(0, A4, nullptr);
    k3_scan<<<BDIM, 128, smem3>>>(h0);
    k_rec<<<NCHUNK, 256, smemR>>>(1, A4, out_hidden);
    k5_known<<<T_STEPS, 128, smemR>>>(A2, out_hidden, out_known);

    (void)in_sizes; (void)n_in; (void)out_size;
}